// round 1
// baseline (speedup 1.0000x reference)
#include <cuda_runtime.h>

// Fixed problem size: In (4,8,262144) f32, NNsites (13,262144) i32,
// Weights (8,8,16) f32, bias (8,8) f32. Output (4,8,262144) f32.
#define NSITES_MAX 262144

// Scratch: site-major transformed features. T[n][bo] and S'[n][bo] (bo = b*8+o),
// each 128 bytes per site -> one cache line per gather.
__device__ __align__(256) float g_T[NSITES_MAX * 32];
__device__ __align__(256) float g_S[NSITES_MAX * 32];

// ---------------------------------------------------------------------------
// Pass 1: S'[n][bo] = sum_i Ws[o][i]*In[b][i][n] + beff[o]
//         T [n][bo] = sum_i Wn[o][i]*In[b][i][n]
// CTA = 256 threads, 32 consecutive sites. Fully coalesced in + out via smem.
// ---------------------------------------------------------------------------
__global__ __launch_bounds__(256) void pass1_kernel(
    const float* __restrict__ In,      // (4,8,N) -> In[(b*8+i)*N + n]
    const float* __restrict__ W,       // (8,8,16) -> W[j*128 + o*16 + k]
    const float* __restrict__ bias,    // (8,8)   -> bias[j*8 + o]
    int N)
{
    __shared__ float sWs[8][8];
    __shared__ float sWn[8][8];
    __shared__ float sbe[8];
    __shared__ float sin_[32][33];   // [r = b*8+i][site]
    __shared__ float soS[32][33];    // [site][bo]
    __shared__ float soT[32][33];

    const int tid  = threadIdx.x;
    const int base = blockIdx.x * 32;

    // Reduce weights over first axis (tiny, per-CTA redundant).
    if (tid < 64) {
        int o = tid >> 3, i = tid & 7;
        float ws = 0.f, wn = 0.f;
        #pragma unroll
        for (int j = 0; j < 8; j++) {
            ws += W[j * 128 + o * 16 + i];
            wn += W[j * 128 + o * 16 + 8 + i];
        }
        sWs[o][i] = ws;
        sWn[o][i] = wn;
        if (i == 0) {
            float be = 0.f;
            #pragma unroll
            for (int j = 0; j < 8; j++) be += bias[j * 8 + o];
            sbe[o] = be;
        }
    }

    // Load input tile: 32 rows (b,i) x 32 sites, coalesced along n.
    #pragma unroll
    for (int k = 0; k < 4; k++) {
        int idx = tid + k * 256;
        int r = idx >> 5, c = idx & 31;
        sin_[r][c] = In[r * N + base + c];
    }
    __syncthreads();

    // Compute: warp w handles bo = w*4 .. w*4+3 (all share b = w>>1), lane = site.
    const int w = tid >> 5, lane = tid & 31;
    const int b = w >> 1;
    float x[8];
    #pragma unroll
    for (int i = 0; i < 8; i++) x[i] = sin_[b * 8 + i][lane];

    #pragma unroll
    for (int q = 0; q < 4; q++) {
        int bo = w * 4 + q;
        int o  = bo & 7;
        float s = sbe[o];
        float t = 0.f;
        #pragma unroll
        for (int i = 0; i < 8; i++) {
            s = fmaf(sWs[o][i], x[i], s);
            t = fmaf(sWn[o][i], x[i], t);
        }
        soS[lane][bo] = s;   // stride-33 across lanes: conflict-free
        soT[lane][bo] = t;
    }
    __syncthreads();

    // Store site-major, coalesced: consecutive tid -> consecutive bo.
    #pragma unroll
    for (int k = 0; k < 4; k++) {
        int idx  = tid + k * 256;
        int site = idx >> 5, bo = idx & 31;
        int off  = (base + site) * 32 + bo;
        g_S[off] = soS[site][bo];
        g_T[off] = soT[site][bo];
    }
}

// ---------------------------------------------------------------------------
// Pass 2: out[bo][n] = sum_z softplus(S'[n][bo] + T[NN[z+1][n]][bo])
// Warp = one site (indices warp-uniform -> 128B coalesced gathers of T).
// Softplus trick: sum softplus(x_z) = sum max(x_z,0) + log( prod (1+e^{-|x_z|}) )
//   -> 1 EX2 per element, 1 LG2 per 12 elements (each factor in (1,2]).
// ---------------------------------------------------------------------------
__global__ __launch_bounds__(256) void pass2_kernel(
    const int* __restrict__ NN,        // (13,N) -> NN[z*N + n]
    float* __restrict__ out,           // (4,8,N) -> out[bo*N + n]
    int N)
{
    __shared__ float so[32][33];       // [site][bo]

    const int tid  = threadIdx.x;
    const int base = blockIdx.x * 32;
    const int w    = tid >> 5, lane = tid & 31;

    #pragma unroll
    for (int q = 0; q < 4; q++) {
        const int sl = w * 4 + q;
        const int n  = base + sl;

        const float s = g_S[n * 32 + lane];

        int idx[12];
        #pragma unroll
        for (int z = 0; z < 12; z++) idx[z] = NN[(z + 1) * N + n];   // warp-uniform

        float t[12];
        #pragma unroll
        for (int z = 0; z < 12; z++) t[z] = g_T[idx[z] * 32 + lane]; // 128B coalesced

        float lin = 0.f;
        float prod = 1.f;
        #pragma unroll
        for (int z = 0; z < 12; z++) {
            float xv = s + t[z];
            lin += fmaxf(xv, 0.f);
            float e = __expf(-fabsf(xv));
            prod *= (1.f + e);
        }
        so[sl][lane] = lin + __logf(prod);
    }
    __syncthreads();

    // Coalesced output: consecutive tid -> consecutive n for fixed bo.
    #pragma unroll
    for (int k = 0; k < 4; k++) {
        int idx  = tid + k * 256;
        int bo   = idx >> 5, site = idx & 31;
        out[bo * N + base + site] = so[site][bo];
    }
}

extern "C" void kernel_launch(void* const* d_in, const int* in_sizes, int n_in,
                              void* d_out, int out_size)
{
    const float* In   = (const float*)d_in[0];
    const int*   NN   = (const int*)  d_in[1];
    const float* W    = (const float*)d_in[2];
    const float* bias = (const float*)d_in[3];
    float*       out  = (float*)d_out;

    const int N = in_sizes[0] / 32;    // 4*8*N elements in In
    const int blocks = N / 32;         // N = 262144 -> 8192 CTAs

    pass1_kernel<<<blocks, 256>>>(In, W, bias, N);
    pass2_kernel<<<blocks, 256>>>(NN, out, N);
}

// round 2
// speedup vs baseline: 1.2949x; 1.2949x over previous
#include <cuda_runtime.h>

// In (4,8,262144) f32, NNsites (13,262144) i32, Weights (8,8,16) f32,
// bias (8,8) f32. Output (4,8,262144) f32.
#define NSITES_MAX 262144

// Site-major neighbor features: T[n][bo], 128 B per site = 1 cache line.
__device__ __align__(256) float g_T[NSITES_MAX * 32];

// ---------------------------------------------------------------------------
// Pass 1: T[n][bo] = sum_i Wn[o][i] * In[b][i][n]      (bo = b*8+o)
// CTA = 256 threads, 32 sites. Coalesced In loads, float4 coalesced T stores.
// ---------------------------------------------------------------------------
__global__ __launch_bounds__(256) void pass1_kernel(
    const float* __restrict__ In,      // In[(b*8+i)*N + n]
    const float* __restrict__ W,       // W[j*128 + o*16 + k]
    int N)
{
    __shared__ float  sWn[8][8];
    __shared__ float  sin_[32][33];    // [r = b*8+i][site]
    __shared__ float4 so4[32][9];      // [site][bo/4], pad -> 36 floats/row

    const int tid  = threadIdx.x;
    const int base = blockIdx.x * 32;

    if (tid < 64) {
        int o = tid >> 3, i = tid & 7;
        float wn = 0.f;
        #pragma unroll
        for (int j = 0; j < 8; j++) wn += W[j * 128 + o * 16 + 8 + i];
        sWn[o][i] = wn;
    }

    #pragma unroll
    for (int k = 0; k < 4; k++) {
        int idx = tid + k * 256;
        int r = idx >> 5, c = idx & 31;
        sin_[r][c] = In[r * N + base + c];
    }
    __syncthreads();

    const int w = tid >> 5, lane = tid & 31;   // lane = site, w -> bo group
    const int b = w >> 1;
    float x[8];
    #pragma unroll
    for (int i = 0; i < 8; i++) x[i] = sin_[b * 8 + i][lane];

    float tv[4];
    #pragma unroll
    for (int q = 0; q < 4; q++) {
        int o = (w * 4 + q) & 7;
        float acc = 0.f;
        #pragma unroll
        for (int i = 0; i < 8; i++) acc = fmaf(sWn[o][i], x[i], acc);
        tv[q] = acc;
    }
    so4[lane][w] = make_float4(tv[0], tv[1], tv[2], tv[3]);
    __syncthreads();

    // Coalesced 128-bit stores: 8 threads cover one site's 128 B row.
    const int site = tid >> 3, j = tid & 7;
    ((float4*)g_T)[(base + site) * 8 + j] = so4[site][j];
}

// ---------------------------------------------------------------------------
// Pass 2: out[bo][n] = sum_z softplus( S[n][bo] + T[NN[z+1][n]][bo] )
//   S recomputed in-CTA from In (saves the g_S round-trip).
// Lane layout: 8 lanes per site, float4 over bo  -> LDG.128 gathers.
// Softplus: sum sp(x) = sum max(x,0) + log( prod (1 + e^{-|x|}) )
//   -> 1 EX2 / element, 1 LG2 / 12 elements. Each factor in (1,2].
// ---------------------------------------------------------------------------
__global__ __launch_bounds__(256) void pass2_kernel(
    const float* __restrict__ In,
    const int*   __restrict__ NN,      // NN[z*N + n]
    const float* __restrict__ W,
    const float* __restrict__ bias,    // bias[j*8 + o]
    float*       __restrict__ out,     // out[bo*N + n]
    int N)
{
    __shared__ float sWs[8][8];
    __shared__ float sbe[8];
    __shared__ float sin_[32][33];
    __shared__ int   sNN[12][32];
    __shared__ float so[32 * 37];      // [site][bo], stride 37 (conflict-free both ways)

    const int tid  = threadIdx.x;
    const int base = blockIdx.x * 32;

    if (tid < 64) {
        int o = tid >> 3, i = tid & 7;
        float ws = 0.f;
        #pragma unroll
        for (int j = 0; j < 8; j++) ws += W[j * 128 + o * 16 + i];
        sWs[o][i] = ws;
        if (i == 0) {
            float be = 0.f;
            #pragma unroll
            for (int j = 0; j < 8; j++) be += bias[j * 8 + o];
            sbe[o] = be;
        }
    }

    #pragma unroll
    for (int k = 0; k < 4; k++) {
        int idx = tid + k * 256;
        int r = idx >> 5, c = idx & 31;
        sin_[r][c] = In[r * N + base + c];
    }
    #pragma unroll
    for (int k = 0; k < 2; k++) {
        int idx = tid + k * 256;
        if (idx < 384) {
            int z = idx >> 5, site = idx & 31;
            sNN[z][site] = NN[(z + 1) * N + base + site];
        }
    }
    __syncthreads();

    const int w    = tid >> 5, lane = tid & 31;
    const int s    = w * 4 + (lane >> 3);   // site within tile
    const int j    = lane & 7;              // float4 group: bo = 4j..4j+3
    const int b    = j >> 1;
    const int o0   = (j & 1) * 4;

    // Recompute S for this (site, bo group): 8 FMA per component.
    float x[8];
    #pragma unroll
    for (int i = 0; i < 8; i++) x[i] = sin_[b * 8 + i][s];

    float sv[4];
    #pragma unroll
    for (int q = 0; q < 4; q++) {
        float acc = sbe[o0 + q];
        #pragma unroll
        for (int i = 0; i < 8; i++) acc = fmaf(sWs[o0 + q][i], x[i], acc);
        sv[q] = acc;
    }

    float lin[4]  = {0.f, 0.f, 0.f, 0.f};
    float prod[4] = {1.f, 1.f, 1.f, 1.f};
    const float4* __restrict__ Tp = (const float4*)g_T;

    #pragma unroll
    for (int zc = 0; zc < 2; zc++) {
        float4 t[6];
        #pragma unroll
        for (int z = 0; z < 6; z++) {
            int idx = sNN[zc * 6 + z][s];          // 4 distinct addrs/warp (LDS bcast)
            t[z] = Tp[idx * 8 + j];                // 128-bit coalesced gather
        }
        #pragma unroll
        for (int z = 0; z < 6; z++) {
            float tv[4] = {t[z].x, t[z].y, t[z].z, t[z].w};
            #pragma unroll
            for (int q = 0; q < 4; q++) {
                float xv = sv[q] + tv[q];
                lin[q] += fmaxf(xv, 0.f);
                prod[q] *= (1.f + __expf(-fabsf(xv)));
            }
        }
    }

    #pragma unroll
    for (int q = 0; q < 4; q++)
        so[s * 37 + j * 4 + q] = lin[q] + __logf(prod[q]);
    __syncthreads();

    #pragma unroll
    for (int k = 0; k < 4; k++) {
        int idx  = tid + k * 256;
        int bo   = idx >> 5, site = idx & 31;
        out[bo * N + base + site] = so[site * 37 + bo];
    }
}

extern "C" void kernel_launch(void* const* d_in, const int* in_sizes, int n_in,
                              void* d_out, int out_size)
{
    const float* In   = (const float*)d_in[0];
    const int*   NN   = (const int*)  d_in[1];
    const float* W    = (const float*)d_in[2];
    const float* bias = (const float*)d_in[3];
    float*       out  = (float*)d_out;

    const int N = in_sizes[0] / 32;
    const int blocks = N / 32;

    pass1_kernel<<<blocks, 256>>>(In, W, N);
    pass2_kernel<<<blocks, 256>>>(In, NN, W, bias, out, N);
}

// round 3
// speedup vs baseline: 1.5374x; 1.1873x over previous
#include <cuda_runtime.h>
#include <cuda_fp16.h>

// In (4,8,262144) f32, NNsites (13,262144) i32, Weights (8,8,16) f32,
// bias (8,8) f32. Output (4,8,262144) f32.
#define NSITES_MAX 262144

// Site-major neighbor features, fp16, PRE-SCALED by log2(e):
// g_T[n][bo] = log2e * sum_i Wn[o][i] * In[b][i][n].  Row = 32 half = 64 B.
__device__ __align__(256) __half2 g_T[NSITES_MAX * 16];

__device__ __forceinline__ __half2 u32_as_h2(unsigned v) {
    return *reinterpret_cast<const __half2*>(&v);
}

// acc (packed f32x2) += {a, b}
__device__ __forceinline__ void acc_f32x2(unsigned long long& acc, float a, float b) {
    unsigned long long t;
    asm("mov.b64 %0, {%1, %2};" : "=l"(t) : "f"(a), "f"(b));
    asm("add.rn.f32x2 %0, %0, %1;" : "+l"(acc) : "l"(t));
}

// ---------------------------------------------------------------------------
// Pass 1: T'[n][bo] = log2e * sum_i Wn[o][i]*In[b][i][n], stored fp16.
// Warp = 4 sites x 8 bo-groups -> direct coalesced 8B stores, no transpose.
// ---------------------------------------------------------------------------
__global__ __launch_bounds__(256) void pass1_kernel(
    const float* __restrict__ In,      // In[(b*8+i)*N + n]
    const float* __restrict__ W,       // W[j*128 + o*16 + k]
    int N)
{
    __shared__ float sWn[8][8];
    __shared__ float sin_[32][33];     // [r = b*8+i][site]

    const int tid  = threadIdx.x;
    const int base = blockIdx.x * 32;

    if (tid < 64) {
        int o = tid >> 3, i = tid & 7;
        float wn = 0.f;
        #pragma unroll
        for (int j = 0; j < 8; j++) wn += W[j * 128 + o * 16 + 8 + i];
        sWn[o][i] = wn * 1.44269504f;   // fold log2e
    }
    #pragma unroll
    for (int k = 0; k < 4; k++) {
        int idx = tid + k * 256;
        int r = idx >> 5, c = idx & 31;
        sin_[r][c] = In[r * N + base + c];
    }
    __syncthreads();

    const int w  = tid >> 5, lane = tid & 31;
    const int sl = w * 4 + (lane >> 3);     // site in tile
    const int j  = lane & 7;                // bo group: 4j..4j+3
    const int b  = j >> 1, o0 = (j & 1) * 4;

    float x[8];
    #pragma unroll
    for (int i = 0; i < 8; i++) x[i] = sin_[b * 8 + i][sl];

    float tv[4];
    #pragma unroll
    for (int q = 0; q < 4; q++) {
        float acc = 0.f;
        #pragma unroll
        for (int i = 0; i < 8; i++) acc = fmaf(sWn[o0 + q][i], x[i], acc);
        tv[q] = acc;
    }
    __half2 h0 = __floats2half2_rn(tv[0], tv[1]);
    __half2 h1 = __floats2half2_rn(tv[2], tv[3]);
    uint2 u = make_uint2(*reinterpret_cast<unsigned*>(&h0),
                         *reinterpret_cast<unsigned*>(&h1));
    ((uint2*)g_T)[(base + sl) * 8 + j] = u;   // 256B contiguous per warp
}

// ---------------------------------------------------------------------------
// Pass 2: out[bo][n] = sum_z softplus( S[n][bo] + T[NN[z+1][n]][bo] )
// All scaled by log2e internally:  x' = log2e * x.
//   sum softplus(x) = (ln2/2) * sum (x' + |x'|) + log( prod (1 + 2^{-|x'|}) )
// Inner math packed half2: HADD2/HABS2/EX2.f16x2/HFMA2 -> ~4 slots/element.
// ---------------------------------------------------------------------------
__global__ __launch_bounds__(256, 5) void pass2_kernel(
    const float* __restrict__ In,
    const int*   __restrict__ NN,      // NN[z*N + n]
    const float* __restrict__ W,
    const float* __restrict__ bias,    // bias[j*8 + o]
    float*       __restrict__ out,     // out[bo*N + n]
    int N)
{
    __shared__ float sWs[8][8];
    __shared__ float sbe[8];
    __shared__ float sin_[32][33];
    __shared__ int   sNN[12][32];
    __shared__ float so[32 * 37];

    const int tid  = threadIdx.x;
    const int base = blockIdx.x * 32;

    if (tid < 64) {
        int o = tid >> 3, i = tid & 7;
        float ws = 0.f;
        #pragma unroll
        for (int j = 0; j < 8; j++) ws += W[j * 128 + o * 16 + i];
        sWs[o][i] = ws * 1.44269504f;           // fold log2e
        if (i == 0) {
            float be = 0.f;
            #pragma unroll
            for (int j = 0; j < 8; j++) be += bias[j * 8 + o];
            sbe[o] = be * 1.44269504f;
        }
    }
    #pragma unroll
    for (int k = 0; k < 4; k++) {
        int idx = tid + k * 256;
        int r = idx >> 5, c = idx & 31;
        sin_[r][c] = In[r * N + base + c];
    }
    #pragma unroll
    for (int k = 0; k < 2; k++) {
        int idx = tid + k * 256;
        if (idx < 384) {
            int z = idx >> 5, site = idx & 31;
            sNN[z][site] = NN[(z + 1) * N + base + site];
        }
    }
    __syncthreads();

    const int w  = tid >> 5, lane = tid & 31;
    const int sl = w * 4 + (lane >> 3);
    const int j  = lane & 7;
    const int b  = j >> 1, o0 = (j & 1) * 4;

    // S' (log2e-scaled) for this (site, bo group), fp32 -> half2.
    float x[8];
    #pragma unroll
    for (int i = 0; i < 8; i++) x[i] = sin_[b * 8 + i][sl];

    float sv[4];
    #pragma unroll
    for (int q = 0; q < 4; q++) {
        float acc = sbe[o0 + q];
        #pragma unroll
        for (int i = 0; i < 8; i++) acc = fmaf(sWs[o0 + q][i], x[i], acc);
        sv[q] = acc;
    }
    const __half2 s20 = __floats2half2_rn(sv[0], sv[1]);
    const __half2 s21 = __floats2half2_rn(sv[2], sv[3]);

    const uint2* __restrict__ Tp = (const uint2*)g_T;

    __half2 prod0 = __floats2half2_rn(1.f, 1.f);
    __half2 prod1 = prod0;
    unsigned long long lin0 = 0ull, lin1 = 0ull;   // packed f32x2 accumulators

    #pragma unroll
    for (int zc = 0; zc < 2; zc++) {
        uint2 t[6];
        #pragma unroll
        for (int z = 0; z < 6; z++) {
            int idx = sNN[zc * 6 + z][sl];         // warp-uniform per 8 lanes
            t[z] = Tp[idx * 8 + j];                // 64B coalesced gather row
        }
        #pragma unroll
        for (int z = 0; z < 6; z++) {
            __half2 t0 = u32_as_h2(t[z].x), t1 = u32_as_h2(t[z].y);
            __half2 x0 = __hadd2(s20, t0),  x1 = __hadd2(s21, t1);
            __half2 a0 = __habs2(x0),       a1 = __habs2(x1);
            __half2 u0 = __hadd2(x0, a0),   u1 = __hadd2(x1, a1);  // 2*max(x',0)
            float2 f0 = __half22float2(u0), f1 = __half22float2(u1);
            acc_f32x2(lin0, f0.x, f0.y);
            acc_f32x2(lin1, f1.x, f1.y);
            __half2 e0 = h2exp2(__hneg2(a0));      // 2^{-|x'|} = e^{-|x|}
            __half2 e1 = h2exp2(__hneg2(a1));
            prod0 = __hfma2(prod0, e0, prod0);     // prod *= (1 + e)
            prod1 = __hfma2(prod1, e1, prod1);
        }
    }

    float l0x, l0y, l1x, l1y;
    asm("mov.b64 {%0, %1}, %2;" : "=f"(l0x), "=f"(l0y) : "l"(lin0));
    asm("mov.b64 {%0, %1}, %2;" : "=f"(l1x), "=f"(l1y) : "l"(lin1));

    const float hln2 = 0.34657359f;  // ln2 / 2  (lin holds 2*max, log2e-scaled)
    float r0 = fmaf(hln2, l0x, __logf(__low2float (prod0)));
    float r1 = fmaf(hln2, l0y, __logf(__high2float(prod0)));
    float r2 = fmaf(hln2, l1x, __logf(__low2float (prod1)));
    float r3 = fmaf(hln2, l1y, __logf(__high2float(prod1)));

    so[sl * 37 + j * 4 + 0] = r0;
    so[sl * 37 + j * 4 + 1] = r1;
    so[sl * 37 + j * 4 + 2] = r2;
    so[sl * 37 + j * 4 + 3] = r3;
    __syncthreads();

    #pragma unroll
    for (int k = 0; k < 4; k++) {
        int idx  = tid + k * 256;
        int bo   = idx >> 5, site = idx & 31;
        out[bo * N + base + site] = so[site * 37 + bo];
    }
}

extern "C" void kernel_launch(void* const* d_in, const int* in_sizes, int n_in,
                              void* d_out, int out_size)
{
    const float* In   = (const float*)d_in[0];
    const int*   NN   = (const int*)  d_in[1];
    const float* W    = (const float*)d_in[2];
    const float* bias = (const float*)d_in[3];
    float*       out  = (float*)d_out;

    const int N = in_sizes[0] / 32;
    const int blocks = N / 32;

    pass1_kernel<<<blocks, 256>>>(In, W, N);
    pass2_kernel<<<blocks, 256>>>(In, NN, W, bias, out, N);
}

// round 4
// speedup vs baseline: 1.6999x; 1.1057x over previous
#include <cuda_runtime.h>
#include <cuda_fp16.h>

// In (4,8,262144) f32, NNsites (13,262144) i32, Weights (8,8,16) f32,
// bias (8,8) f32. Output (4,8,262144) f32.
#define NSITES_MAX 262144

// Site-major neighbor features, fp16, PRE-SCALED by log2(e):
// g_T[n][bo] = log2e * sum_i Wn[o][i] * In[b][i][n].  Row = 32 half = 64 B.
__device__ __align__(256) __half2 g_T[NSITES_MAX * 16];

__device__ __forceinline__ __half2 u32_as_h2(unsigned v) {
    return *reinterpret_cast<const __half2*>(&v);
}

// acc (packed f32x2) += {a, b}
__device__ __forceinline__ void acc_f32x2(unsigned long long& acc, float a, float b) {
    unsigned long long t;
    asm("mov.b64 %0, {%1, %2};" : "=l"(t) : "f"(a), "f"(b));
    asm("add.rn.f32x2 %0, %0, %1;" : "+l"(acc) : "l"(t));
}

// ---------------------------------------------------------------------------
// Pass 1: T'[n][bo] = log2e * sum_i Wn[o][i]*In[b][i][n], stored fp16.
// 128 sites per CTA (grid/4) to amortize launch + weight setup.
// smem stride 129 (odd) -> conflict-free column reads in compute phase.
// ---------------------------------------------------------------------------
__global__ __launch_bounds__(256) void pass1_kernel(
    const float* __restrict__ In,      // In[(b*8+i)*N + n]
    const float* __restrict__ W,       // W[j*128 + o*16 + k]
    int N)
{
    __shared__ float sWn[8][8];
    __shared__ float sin_[32][129];    // [r = b*8+i][site 0..127]

    const int tid  = threadIdx.x;
    const int base = blockIdx.x * 128;

    if (tid < 64) {
        int o = tid >> 3, i = tid & 7;
        float wn = 0.f;
        #pragma unroll
        for (int j = 0; j < 8; j++) wn += W[j * 128 + o * 16 + 8 + i];
        sWn[o][i] = wn * 1.44269504f;   // fold log2e
    }
    #pragma unroll
    for (int k = 0; k < 16; k++) {
        int idx = tid + k * 256;
        int r = idx >> 7, c = idx & 127;
        sin_[r][c] = In[r * N + base + c];
    }
    __syncthreads();

    const int w  = tid >> 5, lane = tid & 31;
    const int j  = lane & 7;                // bo group: 4j..4j+3
    const int b  = j >> 1, o0 = (j & 1) * 4;

    #pragma unroll
    for (int st = 0; st < 4; st++) {
        const int sl = st * 32 + w * 4 + (lane >> 3);   // site in 128-tile

        float x[8];
        #pragma unroll
        for (int i = 0; i < 8; i++) x[i] = sin_[b * 8 + i][sl];

        float tv[4];
        #pragma unroll
        for (int q = 0; q < 4; q++) {
            float acc = 0.f;
            #pragma unroll
            for (int i = 0; i < 8; i++) acc = fmaf(sWn[o0 + q][i], x[i], acc);
            tv[q] = acc;
        }
        __half2 h0 = __floats2half2_rn(tv[0], tv[1]);
        __half2 h1 = __floats2half2_rn(tv[2], tv[3]);
        uint2 u = make_uint2(*reinterpret_cast<unsigned*>(&h0),
                             *reinterpret_cast<unsigned*>(&h1));
        ((uint2*)g_T)[(base + sl) * 8 + j] = u;   // 256B contiguous per warp
    }
}

// ---------------------------------------------------------------------------
// Pass 2: out[bo][n] = sum_z softplus( S[n][bo] + T[NN[z+1][n]][bo] )
// log2e-scaled throughout (x' = log2e * x):
//   sum softplus(x) = ln2 * sum max(x',0) + log( prod (1 + 2^{-|x'|}) )
// Per z (half2):  r  = hfma2_relu(s, 1, t)        = max(x',0)
//                 m  = hfma2(r, -2, t) + s        = -|x'|
//                 e  = ex2.f16x2(m);  prod = hfma2(prod, e, prod)
// lin: pairwise f16 add, then f32x2 accumulate (one convert per 2 z).
// ---------------------------------------------------------------------------
__global__ __launch_bounds__(256, 6) void pass2_kernel(
    const float* __restrict__ In,
    const int*   __restrict__ NN,      // NN[z*N + n]
    const float* __restrict__ W,
    const float* __restrict__ bias,    // bias[j*8 + o]
    float*       __restrict__ out,     // out[bo*N + n]
    int N)
{
    __shared__ float sWs[8][8];
    __shared__ float sbe[8];
    __shared__ float sin_[32][33];
    __shared__ int   sNN[12][32];
    __shared__ float so[32 * 37];

    const int tid  = threadIdx.x;
    const int base = blockIdx.x * 32;

    if (tid < 64) {
        int o = tid >> 3, i = tid & 7;
        float ws = 0.f;
        #pragma unroll
        for (int j = 0; j < 8; j++) ws += W[j * 128 + o * 16 + i];
        sWs[o][i] = ws * 1.44269504f;           // fold log2e
        if (i == 0) {
            float be = 0.f;
            #pragma unroll
            for (int j = 0; j < 8; j++) be += bias[j * 8 + o];
            sbe[o] = be * 1.44269504f;
        }
    }
    #pragma unroll
    for (int k = 0; k < 4; k++) {
        int idx = tid + k * 256;
        int r = idx >> 5, c = idx & 31;
        sin_[r][c] = In[r * N + base + c];
    }
    #pragma unroll
    for (int k = 0; k < 2; k++) {
        int idx = tid + k * 256;
        if (idx < 384) {
            int z = idx >> 5, site = idx & 31;
            sNN[z][site] = NN[(z + 1) * N + base + site];
        }
    }
    __syncthreads();

    const int w  = tid >> 5, lane = tid & 31;
    const int sl = w * 4 + (lane >> 3);
    const int j  = lane & 7;
    const int b  = j >> 1, o0 = (j & 1) * 4;

    // S' (log2e-scaled) for this (site, bo group), fp32 -> half2.
    float x[8];
    #pragma unroll
    for (int i = 0; i < 8; i++) x[i] = sin_[b * 8 + i][sl];

    float sv[4];
    #pragma unroll
    for (int q = 0; q < 4; q++) {
        float acc = sbe[o0 + q];
        #pragma unroll
        for (int i = 0; i < 8; i++) acc = fmaf(sWs[o0 + q][i], x[i], acc);
        sv[q] = acc;
    }
    const __half2 s20 = __floats2half2_rn(sv[0], sv[1]);
    const __half2 s21 = __floats2half2_rn(sv[2], sv[3]);

    const __half2 one2 = __float2half2_rn(1.f);
    const __half2 m22  = __float2half2_rn(-2.f);

    const uint2* __restrict__ Tp = (const uint2*)g_T;

    __half2 prod0 = one2, prod1 = one2;
    unsigned long long lin0 = 0ull, lin1 = 0ull;   // packed f32x2 accumulators

    #pragma unroll
    for (int zc = 0; zc < 3; zc++) {
        uint2 t[4];
        #pragma unroll
        for (int z = 0; z < 4; z++) {
            int idx = sNN[zc * 4 + z][sl];         // uniform per 8 lanes (bcast)
            t[z] = Tp[idx * 8 + j];                // 64B coalesced gather row
        }
        #pragma unroll
        for (int p = 0; p < 2; p++) {
            __half2 ta0 = u32_as_h2(t[p * 2].x),     ta1 = u32_as_h2(t[p * 2].y);
            __half2 tb0 = u32_as_h2(t[p * 2 + 1].x), tb1 = u32_as_h2(t[p * 2 + 1].y);

            __half2 ra0 = __hfma2_relu(s20, one2, ta0);   // max(x',0)
            __half2 ra1 = __hfma2_relu(s21, one2, ta1);
            __half2 rb0 = __hfma2_relu(s20, one2, tb0);
            __half2 rb1 = __hfma2_relu(s21, one2, tb1);

            __half2 ma0 = __hadd2(__hfma2(ra0, m22, ta0), s20);   // -|x'|
            __half2 ma1 = __hadd2(__hfma2(ra1, m22, ta1), s21);
            __half2 mb0 = __hadd2(__hfma2(rb0, m22, tb0), s20);
            __half2 mb1 = __hadd2(__hfma2(rb1, m22, tb1), s21);

            __half2 e;
            e = h2exp2(ma0); prod0 = __hfma2(prod0, e, prod0);    // *= (1+2^m)
            e = h2exp2(ma1); prod1 = __hfma2(prod1, e, prod1);
            e = h2exp2(mb0); prod0 = __hfma2(prod0, e, prod0);
            e = h2exp2(mb1); prod1 = __hfma2(prod1, e, prod1);

            __half2 rp0 = __hadd2(ra0, rb0);       // pair-sum in f16
            __half2 rp1 = __hadd2(ra1, rb1);
            float2 f0 = __half22float2(rp0);
            float2 f1 = __half22float2(rp1);
            acc_f32x2(lin0, f0.x, f0.y);
            acc_f32x2(lin1, f1.x, f1.y);
        }
    }

    float l0x, l0y, l1x, l1y;
    asm("mov.b64 {%0, %1}, %2;" : "=f"(l0x), "=f"(l0y) : "l"(lin0));
    asm("mov.b64 {%0, %1}, %2;" : "=f"(l1x), "=f"(l1y) : "l"(lin1));

    const float ln2 = 0.69314718f;   // lin holds sum of max(x',0), log2e-scaled
    float r0 = fmaf(ln2, l0x, __logf(__low2float (prod0)));
    float r1 = fmaf(ln2, l0y, __logf(__high2float(prod0)));
    float r2 = fmaf(ln2, l1x, __logf(__low2float (prod1)));
    float r3 = fmaf(ln2, l1y, __logf(__high2float(prod1)));

    so[sl * 37 + j * 4 + 0] = r0;
    so[sl * 37 + j * 4 + 1] = r1;
    so[sl * 37 + j * 4 + 2] = r2;
    so[sl * 37 + j * 4 + 3] = r3;
    __syncthreads();

    #pragma unroll
    for (int k = 0; k < 4; k++) {
        int idx  = tid + k * 256;
        int bo   = idx >> 5, site = idx & 31;
        out[bo * N + base + site] = so[site * 37 + bo];
    }
}

extern "C" void kernel_launch(void* const* d_in, const int* in_sizes, int n_in,
                              void* d_out, int out_size)
{
    const float* In   = (const float*)d_in[0];
    const int*   NN   = (const int*)  d_in[1];
    const float* W    = (const float*)d_in[2];
    const float* bias = (const float*)d_in[3];
    float*       out  = (float*)d_out;

    const int N = in_sizes[0] / 32;

    pass1_kernel<<<N / 128, 256>>>(In, W, N);
    pass2_kernel<<<N / 32, 256>>>(In, NN, W, bias, out, N);
}

// round 5
// speedup vs baseline: 1.7382x; 1.0225x over previous
#include <cuda_runtime.h>
#include <cuda_fp16.h>

// In (4,8,262144) f32, NNsites (13,262144) i32, Weights (8,8,16) f32,
// bias (8,8) f32. Output (4,8,262144) f32.
#define NSITES_MAX 262144

// Site-major neighbor features, fp16, PRE-SCALED by log2(e):
// g_T[n][bo] = log2e * sum_i Wn[o][i] * In[b][i][n].  Row = 32 half = 64 B.
__device__ __align__(256) __half2 g_T[NSITES_MAX * 16];

__device__ __forceinline__ __half2 u32_as_h2(unsigned v) {
    return *reinterpret_cast<const __half2*>(&v);
}

// acc (packed f32x2) += {a, b}
__device__ __forceinline__ void acc_f32x2(unsigned long long& acc, float a, float b) {
    unsigned long long t;
    asm("mov.b64 %0, {%1, %2};" : "=l"(t) : "f"(a), "f"(b));
    asm("add.rn.f32x2 %0, %0, %1;" : "+l"(acc) : "l"(t));
}

// ---------------------------------------------------------------------------
// Pass 1: T'[n][bo] = log2e * sum_i Wn[o][i]*In[b][i][n], stored fp16.
// 128 sites per CTA. smem stride 129 -> conflict-free column reads.
// ---------------------------------------------------------------------------
__global__ __launch_bounds__(256) void pass1_kernel(
    const float* __restrict__ In,      // In[(b*8+i)*N + n]
    const float* __restrict__ W,       // W[j*128 + o*16 + k]
    int N)
{
    __shared__ float sWn[8][8];
    __shared__ float sin_[32][129];

    const int tid  = threadIdx.x;
    const int base = blockIdx.x * 128;

    if (tid < 64) {
        int o = tid >> 3, i = tid & 7;
        float wn = 0.f;
        #pragma unroll
        for (int j = 0; j < 8; j++) wn += W[j * 128 + o * 16 + 8 + i];
        sWn[o][i] = wn * 1.44269504f;   // fold log2e
    }
    #pragma unroll
    for (int k = 0; k < 16; k++) {
        int idx = tid + k * 256;
        int r = idx >> 7, c = idx & 127;
        sin_[r][c] = In[r * N + base + c];
    }
    __syncthreads();

    const int w  = tid >> 5, lane = tid & 31;
    const int j  = lane & 7;                // bo group: 4j..4j+3
    const int b  = j >> 1, o0 = (j & 1) * 4;

    #pragma unroll
    for (int st = 0; st < 4; st++) {
        const int sl = st * 32 + w * 4 + (lane >> 3);

        float x[8];
        #pragma unroll
        for (int i = 0; i < 8; i++) x[i] = sin_[b * 8 + i][sl];

        float tv[4];
        #pragma unroll
        for (int q = 0; q < 4; q++) {
            float acc = 0.f;
            #pragma unroll
            for (int i = 0; i < 8; i++) acc = fmaf(sWn[o0 + q][i], x[i], acc);
            tv[q] = acc;
        }
        __half2 h0 = __floats2half2_rn(tv[0], tv[1]);
        __half2 h1 = __floats2half2_rn(tv[2], tv[3]);
        uint2 u = make_uint2(*reinterpret_cast<unsigned*>(&h0),
                             *reinterpret_cast<unsigned*>(&h1));
        ((uint2*)g_T)[(base + sl) * 8 + j] = u;
    }
}

// ---------------------------------------------------------------------------
// Pass 2: out[bo][n] = sum_z softplus( S[n][bo] + T[NN[z+1][n]][bo] )
// log2e-scaled throughout:
//   sum softplus(x) = ln2 * sum max(x',0) + log( prod (1 + 2^{-|x'|}) )
// Lane layout: 4 lanes per site (jj = b = lane&3), 8 sites per warp.
// One uint4 gather per (site, z) = 4 half2 = this thread's 8 bo values.
// CTA = 64 sites, 256 threads.
// ---------------------------------------------------------------------------
__global__ __launch_bounds__(256, 5) void pass2_kernel(
    const float* __restrict__ In,
    const int*   __restrict__ NN,      // NN[z*N + n]
    const float* __restrict__ W,
    const float* __restrict__ bias,    // bias[j*8 + o]
    float*       __restrict__ out,     // out[bo*N + n]
    int N)
{
    __shared__ float sWs[8][8];
    __shared__ float sbe[8];
    __shared__ float sin_[32][65];     // [r = b*8+i][site 0..63]
    __shared__ int   sNN[12][64];
    __shared__ float so[64 * 33];      // [site][bo], stride 33

    const int tid  = threadIdx.x;
    const int base = blockIdx.x * 64;

    if (tid < 64) {
        int o = tid >> 3, i = tid & 7;
        float ws = 0.f;
        #pragma unroll
        for (int j = 0; j < 8; j++) ws += W[j * 128 + o * 16 + i];
        sWs[o][i] = ws * 1.44269504f;           // fold log2e
        if (i == 0) {
            float be = 0.f;
            #pragma unroll
            for (int j = 0; j < 8; j++) be += bias[j * 8 + o];
            sbe[o] = be * 1.44269504f;
        }
    }
    #pragma unroll
    for (int k = 0; k < 8; k++) {
        int idx = tid + k * 256;
        int r = idx >> 6, c = idx & 63;
        sin_[r][c] = In[r * N + base + c];
    }
    #pragma unroll
    for (int k = 0; k < 3; k++) {
        int idx = tid + k * 256;
        int z = idx >> 6, site = idx & 63;
        sNN[z][site] = NN[(z + 1) * N + base + site];
    }
    __syncthreads();

    const int w    = tid >> 5, lane = tid & 31;
    const int sl   = w * 8 + (lane >> 2);   // site within 64-tile
    const int jj   = lane & 3;              // = b ; this thread: bo = jj*8 .. jj*8+7

    // S' (log2e-scaled) for all 8 o of batch b=jj at site sl.
    float x[8];
    #pragma unroll
    for (int i = 0; i < 8; i++) x[i] = sin_[jj * 8 + i][sl];

    float sv[8];
    #pragma unroll
    for (int q = 0; q < 8; q++) {
        float acc = sbe[q];
        #pragma unroll
        for (int i = 0; i < 8; i++) acc = fmaf(sWs[q][i], x[i], acc);
        sv[q] = acc;
    }
    __half2 s2[4];
    #pragma unroll
    for (int m = 0; m < 4; m++) s2[m] = __floats2half2_rn(sv[2 * m], sv[2 * m + 1]);

    const __half2 one2 = __float2half2_rn(1.f);
    const __half2 m22  = __float2half2_rn(-2.f);

    const uint4* __restrict__ Tp = (const uint4*)g_T;

    __half2 prod[4] = {one2, one2, one2, one2};
    unsigned long long lin[4] = {0ull, 0ull, 0ull, 0ull};

    #pragma unroll
    for (int zc = 0; zc < 3; zc++) {
        uint4 t4[4];
        #pragma unroll
        for (int z = 0; z < 4; z++) {
            int idx = sNN[zc * 4 + z][sl];          // uniform across 4 lanes
            t4[z] = Tp[idx * 4 + jj];               // 64B row, 1 LDG.128/site
        }
        #pragma unroll
        for (int p = 0; p < 2; p++) {
            const uint4& ta = t4[p * 2];
            const uint4& tb = t4[p * 2 + 1];
            unsigned tau[4] = {ta.x, ta.y, ta.z, ta.w};
            unsigned tbu[4] = {tb.x, tb.y, tb.z, tb.w};
            #pragma unroll
            for (int m = 0; m < 4; m++) {
                __half2 tha = u32_as_h2(tau[m]);
                __half2 thb = u32_as_h2(tbu[m]);
                __half2 ra = __hfma2_relu(s2[m], one2, tha);   // max(x',0)
                __half2 rb = __hfma2_relu(s2[m], one2, thb);
                __half2 ma = __hadd2(__hfma2(ra, m22, tha), s2[m]);  // -|x'|
                __half2 mb = __hadd2(__hfma2(rb, m22, thb), s2[m]);
                __half2 e;
                e = h2exp2(ma); prod[m] = __hfma2(prod[m], e, prod[m]);
                e = h2exp2(mb); prod[m] = __hfma2(prod[m], e, prod[m]);
                __half2 rp = __hadd2(ra, rb);       // pair-sum in f16
                float2 f = __half22float2(rp);
                acc_f32x2(lin[m], f.x, f.y);
            }
        }
    }

    const float ln2 = 0.69314718f;
    #pragma unroll
    for (int m = 0; m < 4; m++) {
        float lx, ly;
        asm("mov.b64 {%0, %1}, %2;" : "=f"(lx), "=f"(ly) : "l"(lin[m]));
        float r0 = fmaf(ln2, lx, __logf(__low2float (prod[m])));
        float r1 = fmaf(ln2, ly, __logf(__high2float(prod[m])));
        so[sl * 33 + jj * 8 + 2 * m + 0] = r0;
        so[sl * 33 + jj * 8 + 2 * m + 1] = r1;
    }
    __syncthreads();

    #pragma unroll
    for (int k = 0; k < 8; k++) {
        int idx  = tid + k * 256;
        int bo   = idx >> 6, site = idx & 63;
        out[bo * N + base + site] = so[site * 33 + bo];
    }
}

extern "C" void kernel_launch(void* const* d_in, const int* in_sizes, int n_in,
                              void* d_out, int out_size)
{
    const float* In   = (const float*)d_in[0];
    const int*   NN   = (const int*)  d_in[1];
    const float* W    = (const float*)d_in[2];
    const float* bias = (const float*)d_in[3];
    float*       out  = (float*)d_out;

    const int N = in_sizes[0] / 32;

    pass1_kernel<<<N / 128, 256>>>(In, W, N);
    pass2_kernel<<<N / 64, 256>>>(In, NN, W, bias, out, N);
}